// round 6
// baseline (speedup 1.0000x reference)
#include <cuda_runtime.h>
#include <cstdint>
#include <cstddef>

// Problem constants (fixed by the dataset)
#define NV    20000            // vertices per batch
#define NVT   80000            // B * N
#define KN    16               // neighbors
#define MM    9                // kernels
#define CC    64               // in channels
#define OO    64               // out channels

#define NVT_PAD 80128          // padded rows for the GEMM tail tile (313*256)

// Device-global scratch (sanctioned workaround for no-alloc rule)
__device__ float g_uxc[NVT * 12];            // ux + c, padded to 12 floats/vertex
__device__ float g_vxp[NVT * 12];            // vx, padded to 12 floats/vertex
__device__ float g_wt[576 * 64];             // W transposed: Wt[m*64+c][o]
__device__ float g_s[(size_t)NVT_PAD * 576]; // s matrix (inv-deg folded); rows >= NVT stay 0

// ---- packed fp32x2 helpers (Blackwell; ptxas won't auto-fuse these) ----
__device__ __forceinline__ void fma2(unsigned long long& acc,
                                     unsigned long long a,
                                     unsigned long long b) {
    asm("fma.rn.f32x2 %0, %1, %2, %0;" : "+l"(acc) : "l"(a), "l"(b));
}
__device__ __forceinline__ unsigned long long pack2(float x, float y) {
    unsigned long long r;
    asm("mov.b64 %0, {%1, %2};" : "=l"(r) : "f"(x), "f"(y));
    return r;
}
__device__ __forceinline__ float2 unpack2(unsigned long long a) {
    float2 r;
    asm("mov.b64 {%0, %1}, %2;" : "=f"(r.x), "=f"(r.y) : "l"(a));
    return r;
}
// ---- cp.async helpers ----
__device__ __forceinline__ void cpa16(uint32_t dst_smem, const void* src) {
    asm volatile("cp.async.cg.shared.global [%0], [%1], 16;"
                 :: "r"(dst_smem), "l"(src));
}
__device__ __forceinline__ void cpa_commit() {
    asm volatile("cp.async.commit_group;");
}
__device__ __forceinline__ void cpa_wait0() {
    asm volatile("cp.async.wait_group 0;");
}

// ---------------------------------------------------------------------------
// Kernel 1 (merged prep): blocks [0, NVT/8)  -> per-vertex u/v projections
//                         blocks [NVT/8, +144) -> W transpose
// ---------------------------------------------------------------------------
#define UVX_BLOCKS (NVT / 8)

__global__ void __launch_bounds__(256)
feast_prep(const float* __restrict__ x, const float* __restrict__ u,
           const float* __restrict__ v, const float* __restrict__ c,
           const float* __restrict__ W) {
    if (blockIdx.x < UVX_BLOCKS) {
        const int wid  = threadIdx.x >> 5;
        const int lane = threadIdx.x & 31;
        const int gi   = blockIdx.x * 8 + wid;

        const float2 xx = *(const float2*)(x + (size_t)gi * CC + lane * 2);
        #pragma unroll
        for (int m = 0; m < MM; ++m) {
            const float2 uu = *(const float2*)(u + m * CC + lane * 2);
            const float2 vv = *(const float2*)(v + m * CC + lane * 2);
            float pu = xx.x * uu.x + xx.y * uu.y;
            float pv = xx.x * vv.x + xx.y * vv.y;
            #pragma unroll
            for (int off = 16; off > 0; off >>= 1) {
                pu += __shfl_xor_sync(0xffffffffu, pu, off);
                pv += __shfl_xor_sync(0xffffffffu, pv, off);
            }
            if (lane == 0) {
                g_uxc[gi * 12 + m] = pu + c[m];
                g_vxp[gi * 12 + m] = pv;
            }
        }
    } else {
        int tid = (blockIdx.x - UVX_BLOCKS) * 256 + threadIdx.x;
        if (tid >= MM * OO * CC) return;
        int cc = tid & 63;
        int o  = (tid >> 6) & 63;
        int m  = tid >> 12;
        g_wt[(m * 64 + cc) * 64 + o] = W[tid];
    }
}

// ---------------------------------------------------------------------------
// Kernel 2: gather + softmax + s-accumulate  ->  g_s[v][m*64+c]  (scl folded)
// 32 vertices / 256-thread block; tiny smem -> high occupancy.
// ---------------------------------------------------------------------------
__global__ void __launch_bounds__(256)
feast_s(const float* __restrict__ x, const int* __restrict__ adj) {
    __shared__ float q_sm[8 * 384];

    const int tid  = threadIdx.x;
    const int w    = tid >> 5;
    const int lane = tid & 31;
    const int kk   = lane & 15;                 // neighbor slot for stage A
    const int vp   = lane >> 4;                 // vertex-of-pair for stage A
    const int bv0  = blockIdx.x * 32;
    float* qbuf = q_sm + w * 384;

    #pragma unroll
    for (int it = 0; it < 2; ++it) {
        const int vpair = w * 4 + it * 2;

        // ---- stage A: lane (vp, kk) -> softmax over M for one neighbor ----
        const int giA  = bv0 + vpair + vp;
        const int base = (giA / NV) * NV;
        const int a    = adj[giA * KN + kk];
        const unsigned bal = __ballot_sync(0xffffffffu, a > 0);
        const int deg0 = __popc(bal & 0xffffu);
        const int deg1 = __popc(bal >> 16);
        const float validf = (a > 0) ? 1.0f : 0.0f;
        const int j0 = (a > 0) ? (base + a - 1) : base;   // always a valid row

        const float4 uc0 = *(const float4*)(g_uxc + giA * 12);
        const float4 uc1 = *(const float4*)(g_uxc + giA * 12 + 4);
        const float4 uc2 = *(const float4*)(g_uxc + giA * 12 + 8);
        const float4 vv0 = *(const float4*)(g_vxp + j0 * 12);
        const float4 vv1 = *(const float4*)(g_vxp + j0 * 12 + 4);
        const float4 vv2 = *(const float4*)(g_vxp + j0 * 12 + 8);
        float l[9];
        l[0] = (uc0.x + vv0.x) * validf; l[1] = (uc0.y + vv0.y) * validf;
        l[2] = (uc0.z + vv0.z) * validf; l[3] = (uc0.w + vv0.w) * validf;
        l[4] = (uc1.x + vv1.x) * validf; l[5] = (uc1.y + vv1.y) * validf;
        l[6] = (uc1.z + vv1.z) * validf; l[7] = (uc1.w + vv1.w) * validf;
        l[8] = (uc2.x + vv2.x) * validf;
        float mx = l[0];
        #pragma unroll
        for (int m = 1; m < 9; ++m) mx = fmaxf(mx, l[m]);
        float e[9], ssum = 0.f;
        #pragma unroll
        for (int m = 0; m < 9; ++m) { e[m] = __expf(l[m] - mx); ssum += e[m]; }
        float r;
        asm("rcp.approx.f32 %0, %1;" : "=f"(r) : "f"(ssum));
        r *= validf;                                  // invalid neighbor -> q = 0

        float* qk = qbuf + (vp * 16 + kk) * 12;
        *(float4*)(qk)     = make_float4(e[0]*r, e[1]*r, e[2]*r, e[3]*r);
        *(float4*)(qk + 4) = make_float4(e[4]*r, e[5]*r, e[6]*r, e[7]*r);
        *(float4*)(qk + 8) = make_float4(e[8]*r, __int_as_float(j0), 0.f, 0.f);
        __syncwarp();

        // ---- stage B: lane <-> channels (lane, lane+32); branchless gathers ----
        #pragma unroll
        for (int vsel = 0; vsel < 2; ++vsel) {
            const float* qb = qbuf + vsel * 192;
            unsigned long long accA[4] = {0ull,0ull,0ull,0ull};
            unsigned long long accB[4] = {0ull,0ull,0ull,0ull};
            float acc8a = 0.f, acc8b = 0.f;
            #pragma unroll 8
            for (int k2 = 0; k2 < KN; ++k2) {
                const ulonglong2 qp0 = *(const ulonglong2*)(qb + k2 * 12);
                const ulonglong2 qp1 = *(const ulonglong2*)(qb + k2 * 12 + 4);
                const float2     qt  = *(const float2*)(qb + k2 * 12 + 8);
                const int j2 = __float_as_int(qt.y);      // always valid; q==0 if pad
                const float x0 = x[j2 * CC + lane];
                const float x1 = x[j2 * CC + lane + 32];
                const unsigned long long xx0 = pack2(x0, x0);
                const unsigned long long xx1 = pack2(x1, x1);
                fma2(accA[0], qp0.x, xx0); fma2(accA[1], qp0.y, xx0);
                fma2(accA[2], qp1.x, xx0); fma2(accA[3], qp1.y, xx0);
                fma2(accB[0], qp0.x, xx1); fma2(accB[1], qp0.y, xx1);
                fma2(accB[2], qp1.x, xx1); fma2(accB[3], qp1.y, xx1);
                acc8a = fmaf(qt.x, x0, acc8a);
                acc8b = fmaf(qt.x, x1, acc8b);
            }
            const int dg = vsel ? deg1 : deg0;
            const float scl = (dg > 0) ? (1.0f / (float)dg) : 0.0f;
            float* srow = g_s + (size_t)(bv0 + vpair + vsel) * 576;
            #pragma unroll
            for (int mp = 0; mp < 4; ++mp) {
                const float2 a0 = unpack2(accA[mp]);
                const float2 b0 = unpack2(accB[mp]);
                srow[(2*mp)   * 64 + lane]      = a0.x * scl;
                srow[(2*mp+1) * 64 + lane]      = a0.y * scl;
                srow[(2*mp)   * 64 + lane + 32] = b0.x * scl;
                srow[(2*mp+1) * 64 + lane + 32] = b0.y * scl;
            }
            srow[8 * 64 + lane]      = acc8a * scl;
            srow[8 * 64 + lane + 32] = acc8b * scl;
        }
        __syncwarp();
    }
}

// ---------------------------------------------------------------------------
// Kernel 3: out[80000,64] = g_s[.,576] @ g_wt[576,64] + bias
// 256-row x 64-col tiles, 256 threads, thread = 8x8 (full K, no reduce).
// s/wt K-chunks (32) double-buffered via cp.async.
// s smem layout: rowgroup-padded: addr = rg*264 + r8*32 + k  (rg banks distinct)
// ---------------------------------------------------------------------------
#define SGRP   264                        // 8*32 + 8 floats per rowgroup
#define SBUF_F (32 * SGRP)                // 8448 floats per s buffer
#define WBUF_F (32 * 64)                  // 2048 floats per wt buffer

__global__ void __launch_bounds__(256, 2)
feast_gemm(const float* __restrict__ bias, float* __restrict__ out) {
    extern __shared__ float sm[];
    float* sbuf[2] = { sm, sm + SBUF_F };
    float* wbuf[2] = { sm + 2 * SBUF_F, sm + 2 * SBUF_F + WBUF_F };

    const int tid  = threadIdx.x;
    const int w    = tid >> 5;
    const int lane = tid & 31;
    const int cg   = lane & 7;            // col group: cols {4cg..+3, 32+4cg..+3}
    const int rgl  = lane >> 3;           // 4 rowgroups per warp
    const int rowgrp = w * 4 + rgl;       // 0..31
    const size_t row0 = (size_t)blockIdx.x * 256;

    // stage chunk `ch` into buffers buf
    auto stage = [&](int ch, int b) {
        const uint32_t sdst = (uint32_t)__cvta_generic_to_shared(sbuf[b]);
        const uint32_t wdst = (uint32_t)__cvta_generic_to_shared(wbuf[b]);
        const float* ssrc = g_s + row0 * 576 + ch * 32;
        #pragma unroll
        for (int i = 0; i < 8; ++i) {
            const int idx  = tid + i * 256;     // 2048 pieces of 16 B
            const int row  = idx >> 3;
            const int koff = idx & 7;
            const uint32_t d = sdst + ((row >> 3) * SGRP + (row & 7) * 32) * 4 + koff * 16;
            cpa16(d, ssrc + (size_t)row * 576 + koff * 4);
        }
        const float* wsrc = g_wt + ch * (32 * 64);
        #pragma unroll
        for (int i = 0; i < 2; ++i) {
            const int idx = tid + i * 256;      // 512 pieces of 16 B
            cpa16(wdst + idx * 16, wsrc + idx * 4);
        }
        cpa_commit();
    };

    unsigned long long acc[8][4];
    #pragma unroll
    for (int i = 0; i < 8; ++i)
        #pragma unroll
        for (int p = 0; p < 4; ++p) acc[i][p] = 0ull;

    stage(0, 0);

    for (int ch = 0; ch < 18; ++ch) {
        cpa_wait0();
        __syncthreads();                      // chunk ch resident; other buf free

        if (ch < 17) stage(ch + 1, (ch + 1) & 1);

        const float* sb = sbuf[ch & 1] + rowgrp * SGRP;
        const float* wb = wbuf[ch & 1];
        #pragma unroll 8
        for (int k = 0; k < 32; ++k) {
            const float* wrow = wb + k * 64;
            const ulonglong2 wLo = *(const ulonglong2*)(wrow + cg * 4);
            const ulonglong2 wHi = *(const ulonglong2*)(wrow + 32 + cg * 4);
            #pragma unroll
            for (int i = 0; i < 8; ++i) {
                const float sv = sb[i * 32 + k];
                const unsigned long long ss = pack2(sv, sv);
                fma2(acc[i][0], ss, wLo.x);
                fma2(acc[i][1], ss, wLo.y);
                fma2(acc[i][2], ss, wHi.x);
                fma2(acc[i][3], ss, wHi.y);
            }
        }
        __syncthreads();                      // done reading this buf
    }

    // ---- epilogue: add bias, store (guard the tail tile) ----
    const float4 b0 = *(const float4*)(bias + cg * 4);
    const float4 b1 = *(const float4*)(bias + 32 + cg * 4);
    #pragma unroll
    for (int i = 0; i < 8; ++i) {
        const size_t row = row0 + rowgrp * 8 + i;
        if (row < NVT) {
            const float2 f0 = unpack2(acc[i][0]), f1 = unpack2(acc[i][1]);
            const float2 f2 = unpack2(acc[i][2]), f3 = unpack2(acc[i][3]);
            float* op = out + row * OO;
            *(float4*)(op + cg * 4)      = make_float4(f0.x + b0.x, f0.y + b0.y,
                                                       f1.x + b0.z, f1.y + b0.w);
            *(float4*)(op + 32 + cg * 4) = make_float4(f2.x + b1.x, f2.y + b1.y,
                                                       f3.x + b1.z, f3.y + b1.w);
        }
    }
}

// ---------------------------------------------------------------------------
// Host launcher (graph-capturable: kernel launches only)
// ---------------------------------------------------------------------------
extern "C" void kernel_launch(void* const* d_in, const int* in_sizes, int n_in,
                              void* d_out, int out_size) {
    const float* x   = (const float*)d_in[0];  // [B,N,C]
    const int*   adj = (const int*)  d_in[1];  // [B,N,K]
    const float* W   = (const float*)d_in[2];  // [M,O,C]
    const float* b   = (const float*)d_in[3];  // [O]
    const float* u   = (const float*)d_in[4];  // [M,C]
    const float* v   = (const float*)d_in[5];  // [M,C]
    const float* c   = (const float*)d_in[6];  // [M]
    float* out = (float*)d_out;

    feast_prep<<<UVX_BLOCKS + (MM * OO * CC + 255) / 256, 256>>>(x, u, v, c, W);
    feast_s<<<NVT / 32, 256>>>(x, adj);

    const size_t smem_bytes = (size_t)(2 * SBUF_F + 2 * WBUF_F) * sizeof(float); // 83968
    cudaFuncSetAttribute(feast_gemm, cudaFuncAttributeMaxDynamicSharedMemorySize,
                         (int)smem_bytes);
    feast_gemm<<<NVT_PAD / 256, 256, smem_bytes>>>(b, out);
}

// round 9
// speedup vs baseline: 1.7253x; 1.7253x over previous
#include <cuda_runtime.h>
#include <cuda_bf16.h>
#include <cstdint>
#include <cstddef>

// Problem constants (fixed by the dataset)
#define NV    20000            // vertices per batch
#define NVT   80000            // B * N
#define KN    16               // neighbors
#define MM    9                // kernels
#define CC    64               // in channels
#define OO    64               // out channels
#define GK    576              // GEMM K (M * C), tf32 path: no split

// Device-global scratch (sanctioned workaround for no-alloc rule)
__device__ float g_uxc[NVT * 12];                      // ux + c (pad 12)
__device__ float g_vxp[NVT * 12];                      // vx     (pad 12)
__device__ __align__(16) float g_s[(size_t)NVT * GK];  // s (tf32-rounded fp32)
__device__ __align__(16) float g_wb[OO * GK];          // B[o][k] = W[m][o][c], tf32-rounded

// ---- packed fp32x2 helpers ----
__device__ __forceinline__ void fma2(unsigned long long& acc,
                                     unsigned long long a,
                                     unsigned long long b) {
    asm("fma.rn.f32x2 %0, %1, %2, %0;" : "+l"(acc) : "l"(a), "l"(b));
}
__device__ __forceinline__ unsigned long long pack2(float x, float y) {
    unsigned long long r;
    asm("mov.b64 %0, {%1, %2};" : "=l"(r) : "f"(x), "f"(y));
    return r;
}
__device__ __forceinline__ float2 unpack2(unsigned long long a) {
    float2 r;
    asm("mov.b64 {%0, %1}, %2;" : "=f"(r.x), "=f"(r.y) : "l"(a));
    return r;
}
// ---- tf32 round-to-nearest (store pre-rounded so MMA inputs are RN) ----
__device__ __forceinline__ float tf32r(float f) {
    uint32_t r;
    asm("cvt.rna.tf32.f32 %0, %1;" : "=r"(r) : "f"(f));
    return __uint_as_float(r);
}
// ---- cp.async helpers ----
__device__ __forceinline__ void cpa16(uint32_t dst_smem, const void* src) {
    asm volatile("cp.async.cg.shared.global [%0], [%1], 16;"
                 :: "r"(dst_smem), "l"(src));
}
__device__ __forceinline__ void cpa_commit() {
    asm volatile("cp.async.commit_group;");
}
__device__ __forceinline__ void cpa_wait0() {
    asm volatile("cp.async.wait_group 0;");
}
__device__ __forceinline__ uint32_t smem_u32(const void* p) {
    uint32_t a;
    asm("{ .reg .u64 t; cvta.to.shared.u64 t, %1; cvt.u32.u64 %0, t; }"
        : "=r"(a) : "l"(p));
    return a;
}
// ---- tensor-core primitives (baseline PTX, sm_80+) ----
__device__ __forceinline__ void ldsm4(uint32_t& r0, uint32_t& r1, uint32_t& r2,
                                      uint32_t& r3, uint32_t addr) {
    asm volatile("ldmatrix.sync.aligned.m8n8.x4.shared.b16 {%0,%1,%2,%3}, [%4];"
                 : "=r"(r0), "=r"(r1), "=r"(r2), "=r"(r3) : "r"(addr));
}
__device__ __forceinline__ void mma1688(float* c, uint32_t a0, uint32_t a1,
                                        uint32_t a2, uint32_t a3,
                                        uint32_t b0, uint32_t b1) {
    asm volatile(
        "mma.sync.aligned.m16n8k8.row.col.f32.tf32.tf32.f32 "
        "{%0,%1,%2,%3}, {%4,%5,%6,%7}, {%8,%9}, {%0,%1,%2,%3};"
        : "+f"(c[0]), "+f"(c[1]), "+f"(c[2]), "+f"(c[3])
        : "r"(a0), "r"(a1), "r"(a2), "r"(a3), "r"(b0), "r"(b1));
}

// ---------------------------------------------------------------------------
// Kernel 1 (merged prep): blocks [0, NVT/32) -> u/v projections (shuffle-lite)
//                         blocks [NVT/32, +144) -> W -> tf32 B matrix [o][k]
// ---------------------------------------------------------------------------
#define UVX_BLOCKS (NVT / 32)

__global__ void __launch_bounds__(256)
feast_prep(const float* __restrict__ x, const float* __restrict__ u,
           const float* __restrict__ v, const float* __restrict__ c,
           const float* __restrict__ W) {
    if (blockIdx.x < UVX_BLOCKS) {
        __shared__ float uv_sm[18 * 64];
        for (int i = threadIdx.x; i < 576; i += 256) {
            uv_sm[i]       = u[i];
            uv_sm[576 + i] = v[i];
        }
        __syncthreads();

        const int w    = threadIdx.x >> 5;
        const int lane = threadIdx.x & 31;
        const int vsub = lane >> 3;                // vertex within warp group of 4
        const int oct  = lane & 7;                 // channel octet
        const int gi   = blockIdx.x * 32 + w * 4 + vsub;

        const float4 xa = *(const float4*)(x + (size_t)gi * CC + oct * 8);
        const float4 xb = *(const float4*)(x + (size_t)gi * CC + oct * 8 + 4);
        #pragma unroll
        for (int m = 0; m < MM; ++m) {
            const float4 ua = *(const float4*)(uv_sm + m * 64 + oct * 8);
            const float4 ub = *(const float4*)(uv_sm + m * 64 + oct * 8 + 4);
            const float4 va = *(const float4*)(uv_sm + 576 + m * 64 + oct * 8);
            const float4 vb = *(const float4*)(uv_sm + 576 + m * 64 + oct * 8 + 4);
            float pu = xa.x*ua.x + xa.y*ua.y + xa.z*ua.z + xa.w*ua.w
                     + xb.x*ub.x + xb.y*ub.y + xb.z*ub.z + xb.w*ub.w;
            float pv = xa.x*va.x + xa.y*va.y + xa.z*va.z + xa.w*va.w
                     + xb.x*vb.x + xb.y*vb.y + xb.z*vb.z + xb.w*vb.w;
            pu += __shfl_xor_sync(0xffffffffu, pu, 1);
            pv += __shfl_xor_sync(0xffffffffu, pv, 1);
            pu += __shfl_xor_sync(0xffffffffu, pu, 2);
            pv += __shfl_xor_sync(0xffffffffu, pv, 2);
            pu += __shfl_xor_sync(0xffffffffu, pu, 4);
            pv += __shfl_xor_sync(0xffffffffu, pv, 4);
            if (oct == 0) {
                g_uxc[gi * 12 + m] = pu + c[m];
                g_vxp[gi * 12 + m] = pv;
            }
        }
    } else {
        const int tid = (blockIdx.x - UVX_BLOCKS) * 256 + threadIdx.x;
        if (tid >= MM * OO * CC) return;
        const int cc = tid & 63;
        const int o  = (tid >> 6) & 63;
        const int m  = tid >> 12;
        g_wb[o * GK + m * 64 + cc] = tf32r(W[tid]);
    }
}

// ---------------------------------------------------------------------------
// Kernel 2: gather + softmax + s-accumulate -> g_s (tf32-rounded, scl folded)
// ---------------------------------------------------------------------------
__global__ void __launch_bounds__(256)
feast_s(const float* __restrict__ x, const int* __restrict__ adj) {
    __shared__ float q_sm[8 * 384];

    const int tid  = threadIdx.x;
    const int w    = tid >> 5;
    const int lane = tid & 31;
    const int kk   = lane & 15;
    const int vp   = lane >> 4;
    const int bv0  = blockIdx.x * 32;
    float* qbuf = q_sm + w * 384;

    #pragma unroll
    for (int it = 0; it < 2; ++it) {
        const int vpair = w * 4 + it * 2;

        // ---- stage A: lane (vp, kk) -> softmax over M for one neighbor ----
        const int giA  = bv0 + vpair + vp;
        const int base = (giA / NV) * NV;
        const int a    = adj[giA * KN + kk];
        const unsigned bal = __ballot_sync(0xffffffffu, a > 0);
        const int deg0 = __popc(bal & 0xffffu);
        const int deg1 = __popc(bal >> 16);
        const float validf = (a > 0) ? 1.0f : 0.0f;
        const int j0 = (a > 0) ? (base + a - 1) : base;

        const float4 uc0 = *(const float4*)(g_uxc + giA * 12);
        const float4 uc1 = *(const float4*)(g_uxc + giA * 12 + 4);
        const float4 uc2 = *(const float4*)(g_uxc + giA * 12 + 8);
        const float4 vv0 = *(const float4*)(g_vxp + j0 * 12);
        const float4 vv1 = *(const float4*)(g_vxp + j0 * 12 + 4);
        const float4 vv2 = *(const float4*)(g_vxp + j0 * 12 + 8);
        float l[9];
        l[0] = (uc0.x + vv0.x) * validf; l[1] = (uc0.y + vv0.y) * validf;
        l[2] = (uc0.z + vv0.z) * validf; l[3] = (uc0.w + vv0.w) * validf;
        l[4] = (uc1.x + vv1.x) * validf; l[5] = (uc1.y + vv1.y) * validf;
        l[6] = (uc1.z + vv1.z) * validf; l[7] = (uc1.w + vv1.w) * validf;
        l[8] = (uc2.x + vv2.x) * validf;
        float mx = l[0];
        #pragma unroll
        for (int m = 1; m < 9; ++m) mx = fmaxf(mx, l[m]);
        float e[9], ssum = 0.f;
        #pragma unroll
        for (int m = 0; m < 9; ++m) { e[m] = __expf(l[m] - mx); ssum += e[m]; }
        float r;
        asm("rcp.approx.f32 %0, %1;" : "=f"(r) : "f"(ssum));
        r *= validf;

        float* qk = qbuf + (vp * 16 + kk) * 12;
        *(float4*)(qk)     = make_float4(e[0]*r, e[1]*r, e[2]*r, e[3]*r);
        *(float4*)(qk + 4) = make_float4(e[4]*r, e[5]*r, e[6]*r, e[7]*r);
        *(float4*)(qk + 8) = make_float4(e[8]*r, __int_as_float(j0), 0.f, 0.f);
        __syncwarp();

        // ---- stage B: lane <-> channels (lane, lane+32); branchless gathers ----
        #pragma unroll
        for (int vsel = 0; vsel < 2; ++vsel) {
            const float* qb = qbuf + vsel * 192;
            unsigned long long accA[4] = {0ull,0ull,0ull,0ull};
            unsigned long long accB[4] = {0ull,0ull,0ull,0ull};
            float acc8a = 0.f, acc8b = 0.f;
            #pragma unroll 8
            for (int k2 = 0; k2 < KN; ++k2) {
                const ulonglong2 qp0 = *(const ulonglong2*)(qb + k2 * 12);
                const ulonglong2 qp1 = *(const ulonglong2*)(qb + k2 * 12 + 4);
                const float2     qt  = *(const float2*)(qb + k2 * 12 + 8);
                const int j2 = __float_as_int(qt.y);
                const float x0 = x[j2 * CC + lane];
                const float x1 = x[j2 * CC + lane + 32];
                const unsigned long long xx0 = pack2(x0, x0);
                const unsigned long long xx1 = pack2(x1, x1);
                fma2(accA[0], qp0.x, xx0); fma2(accA[1], qp0.y, xx0);
                fma2(accA[2], qp1.x, xx0); fma2(accA[3], qp1.y, xx0);
                fma2(accB[0], qp0.x, xx1); fma2(accB[1], qp0.y, xx1);
                fma2(accB[2], qp1.x, xx1); fma2(accB[3], qp1.y, xx1);
                acc8a = fmaf(qt.x, x0, acc8a);
                acc8b = fmaf(qt.x, x1, acc8b);
            }
            const int dg = vsel ? deg1 : deg0;
            const float scl = (dg > 0) ? (1.0f / (float)dg) : 0.0f;
            float* srow = g_s + (size_t)(bv0 + vpair + vsel) * GK;
            #pragma unroll
            for (int mp = 0; mp < 4; ++mp) {
                const float2 a0 = unpack2(accA[mp]);
                const float2 b0 = unpack2(accB[mp]);
                srow[(2*mp)   * 64 + lane]      = tf32r(a0.x * scl);
                srow[(2*mp+1) * 64 + lane]      = tf32r(a0.y * scl);
                srow[(2*mp)   * 64 + lane + 32] = tf32r(b0.x * scl);
                srow[(2*mp+1) * 64 + lane + 32] = tf32r(b0.y * scl);
            }
            srow[8 * 64 + lane]      = tf32r(acc8a * scl);
            srow[8 * 64 + lane + 32] = tf32r(acc8b * scl);
        }
        __syncwarp();
    }
}

// ---------------------------------------------------------------------------
// Kernel 3: tf32 HMMA GEMM  out[80000,64] = g_s[.,576] @ g_wb^T + bias
// 128-row x 64-col CTA tile, 8 warps (warp = 16 rows x 64 cols), K chunks of
// 32, cp.async double-buffered, SW128-swizzled smem, ldmatrix.x4 frags.
// (byte-level layout identical to the functionally-validated round-8 kernel)
// ---------------------------------------------------------------------------
#define ACHB 16384                       // A chunk: 128 rows x 128 B (32 tf32)
#define BCHB 8192                        // B chunk:  64 rows x 128 B
#define PERBUF (ACHB + BCHB)             // 24576
#define GSMEM (2 * PERBUF + 1024)        // + 1024 alignment slack

__global__ void __launch_bounds__(256, 2)
feast_gemm(const float* __restrict__ bias, float* __restrict__ out) {
    extern __shared__ char smem[];
    const uint32_t sraw = smem_u32(smem);
    const uint32_t sb   = (sraw + 1023u) & ~1023u;     // SW128 needs 1KB align
    const uint32_t abase[2] = { sb, sb + PERBUF };
    const uint32_t bbase[2] = { sb + ACHB, sb + PERBUF + ACHB };

    const int tid  = threadIdx.x;
    const int w    = tid >> 5;
    const int lane = tid & 31;
    const int row0 = blockIdx.x * 128;

    // ldmatrix lane addressing (shared by A and B tiles; 32-bit-data trick)
    const int grp = lane >> 3;                 // 0..3 -> matrix index
    const int rr  = lane & 7;                  // row within matrix
    const int mrow = (grp & 1) * 8 + rr;       // row offset within 16-row group
    const int mcol = (grp >> 1) * 16;          // byte col offset (0 or 16)

    // stage K-chunk ch (32 tf32 columns) into buffer b
    auto stage = [&](int ch, int b) {
        const float* asrc = g_s + (size_t)row0 * GK + ch * 32;
        #pragma unroll
        for (int i = 0; i < 4; ++i) {
            const int uu = tid + i * 256;          // 1024 16B units
            const int row = uu >> 3, cu = uu & 7;
            uint32_t off = (uint32_t)(row * 128 + cu * 16);
            off ^= (off >> 3) & 0x70;
            cpa16(abase[b] + off, asrc + (size_t)row * GK + cu * 4);
        }
        const float* bsrc = g_wb + ch * 32;
        #pragma unroll
        for (int i = 0; i < 2; ++i) {
            const int uu = tid + i * 256;          // 512 16B units
            const int row = uu >> 3, cu = uu & 7;
            uint32_t off = (uint32_t)(row * 128 + cu * 16);
            off ^= (off >> 3) & 0x70;
            cpa16(bbase[b] + off, bsrc + (size_t)row * GK + cu * 4);
        }
        cpa_commit();
    };

    float acc[8][4];
    #pragma unroll
    for (int j = 0; j < 8; ++j)
        #pragma unroll
        for (int p = 0; p < 4; ++p) acc[j][p] = 0.f;

    stage(0, 0);

    for (int ch = 0; ch < 18; ++ch) {
        cpa_wait0();
        __syncthreads();                       // chunk ch resident; prev buf free

        if (ch < 17) stage(ch + 1, (ch + 1) & 1);

        const uint32_t ab = abase[ch & 1];
        const uint32_t bb = bbase[ch & 1];
        #pragma unroll
        for (int k8 = 0; k8 < 4; ++k8) {       // 8 tf32 K per step = 32 bytes
            uint32_t aoff = (uint32_t)((w * 16 + mrow) * 128 + mcol + k8 * 32);
            aoff ^= (aoff >> 3) & 0x70;
            uint32_t a0, a1, a2, a3;
            ldsm4(a0, a1, a2, a3, ab + aoff);
            #pragma unroll
            for (int ng = 0; ng < 4; ++ng) {   // n in groups of 16
                uint32_t boff = (uint32_t)((ng * 16 + mrow) * 128 + mcol + k8 * 32);
                boff ^= (boff >> 3) & 0x70;
                uint32_t b0, b1, b2, b3;
                ldsm4(b0, b1, b2, b3, bb + boff);
                mma1688(acc[ng * 2],     a0, a1, a2, a3, b0, b2);
                mma1688(acc[ng * 2 + 1], a0, a1, a2, a3, b1, b3);
            }
        }
    }

    // ---- epilogue: C frags + bias -> gmem ----
    const int crow = row0 + w * 16 + (lane >> 2);
    const int ccol = (lane & 3) * 2;
    #pragma unroll
    for (int j = 0; j < 8; ++j) {
        const int nb = (j >> 1) * 16 + (j & 1) * 8 + ccol;
        const float2 bv = *(const float2*)(bias + nb);
        *(float2*)(out + (size_t)crow * OO + nb) =
            make_float2(acc[j][0] + bv.x, acc[j][1] + bv.y);
        *(float2*)(out + (size_t)(crow + 8) * OO + nb) =
            make_float2(acc[j][2] + bv.x, acc[j][3] + bv.y);
    }
}

// ---------------------------------------------------------------------------
// Host launcher (graph-capturable: kernel launches only)
// ---------------------------------------------------------------------------
extern "C" void kernel_launch(void* const* d_in, const int* in_sizes, int n_in,
                              void* d_out, int out_size) {
    const float* x   = (const float*)d_in[0];  // [B,N,C]
    const int*   adj = (const int*)  d_in[1];  // [B,N,K]
    const float* W   = (const float*)d_in[2];  // [M,O,C]
    const float* b   = (const float*)d_in[3];  // [O]
    const float* u   = (const float*)d_in[4];  // [M,C]
    const float* v   = (const float*)d_in[5];  // [M,C]
    const float* c   = (const float*)d_in[6];  // [M]
    float* out = (float*)d_out;

    feast_prep<<<UVX_BLOCKS + (MM * OO * CC + 255) / 256, 256>>>(x, u, v, c, W);
    feast_s<<<NVT / 32, 256>>>(x, adj);

    cudaFuncSetAttribute(feast_gemm, cudaFuncAttributeMaxDynamicSharedMemorySize,
                         GSMEM);
    feast_gemm<<<NVT / 128, 256, GSMEM>>>(b, out);
}

// round 10
// speedup vs baseline: 2.2383x; 1.2974x over previous
#include <cuda_runtime.h>
#include <cuda_fp16.h>
#include <cstdint>
#include <cstddef>

// Problem constants (fixed by the dataset)
#define NV    20000            // vertices per batch
#define NVT   80000            // B * N
#define KN    16               // neighbors
#define MM    9                // kernels
#define CC    64               // in channels
#define OO    64               // out channels
#define GK    576              // GEMM K (M * C)

// Device-global scratch (sanctioned workaround for no-alloc rule)
__device__ float g_uxc[NVT * 12];                       // ux + c (pad 12)
__device__ float g_vxp[NVT * 12];                       // vx     (pad 12)
__device__ __align__(16) __half g_s[(size_t)NVT * GK];  // s (fp16, scl folded)
__device__ __align__(16) __half g_wb[OO * GK];          // B[o][k] = W[m][o][c]

// ---- packed fp32x2 helpers ----
__device__ __forceinline__ void fma2(unsigned long long& acc,
                                     unsigned long long a,
                                     unsigned long long b) {
    asm("fma.rn.f32x2 %0, %1, %2, %0;" : "+l"(acc) : "l"(a), "l"(b));
}
__device__ __forceinline__ unsigned long long pack2(float x, float y) {
    unsigned long long r;
    asm("mov.b64 %0, {%1, %2};" : "=l"(r) : "f"(x), "f"(y));
    return r;
}
__device__ __forceinline__ float2 unpack2(unsigned long long a) {
    float2 r;
    asm("mov.b64 {%0, %1}, %2;" : "=f"(r.x), "=f"(r.y) : "l"(a));
    return r;
}
// ---- cp.async helpers ----
__device__ __forceinline__ void cpa16(uint32_t dst_smem, const void* src) {
    asm volatile("cp.async.cg.shared.global [%0], [%1], 16;"
                 :: "r"(dst_smem), "l"(src));
}
__device__ __forceinline__ void cpa_commit() {
    asm volatile("cp.async.commit_group;");
}
__device__ __forceinline__ void cpa_wait0() {
    asm volatile("cp.async.wait_group 0;");
}
__device__ __forceinline__ uint32_t smem_u32(const void* p) {
    uint32_t a;
    asm("{ .reg .u64 t; cvta.to.shared.u64 t, %1; cvt.u32.u64 %0, t; }"
        : "=r"(a) : "l"(p));
    return a;
}
// ---- tensor-core primitives (baseline PTX, sm_80+) ----
__device__ __forceinline__ void ldsm4(uint32_t& r0, uint32_t& r1, uint32_t& r2,
                                      uint32_t& r3, uint32_t addr) {
    asm volatile("ldmatrix.sync.aligned.m8n8.x4.shared.b16 {%0,%1,%2,%3}, [%4];"
                 : "=r"(r0), "=r"(r1), "=r"(r2), "=r"(r3) : "r"(addr));
}
__device__ __forceinline__ void mma16816(float* c, uint32_t a0, uint32_t a1,
                                         uint32_t a2, uint32_t a3,
                                         uint32_t b0, uint32_t b1) {
    asm volatile(
        "mma.sync.aligned.m16n8k16.row.col.f32.f16.f16.f32 "
        "{%0,%1,%2,%3}, {%4,%5,%6,%7}, {%8,%9}, {%0,%1,%2,%3};"
        : "+f"(c[0]), "+f"(c[1]), "+f"(c[2]), "+f"(c[3])
        : "r"(a0), "r"(a1), "r"(a2), "r"(a3), "r"(b0), "r"(b1));
}

// ---------------------------------------------------------------------------
// Kernel 1 (merged prep): blocks [0, NVT/32) -> u/v projections (shuffle-lite)
//                         blocks [NVT/32, +144) -> W -> fp16 B matrix [o][k]
// ---------------------------------------------------------------------------
#define UVX_BLOCKS (NVT / 32)

__global__ void __launch_bounds__(256)
feast_prep(const float* __restrict__ x, const float* __restrict__ u,
           const float* __restrict__ v, const float* __restrict__ c,
           const float* __restrict__ W) {
    if (blockIdx.x < UVX_BLOCKS) {
        __shared__ float uv_sm[18 * 64];
        for (int i = threadIdx.x; i < 576; i += 256) {
            uv_sm[i]       = u[i];
            uv_sm[576 + i] = v[i];
        }
        __syncthreads();

        const int w    = threadIdx.x >> 5;
        const int lane = threadIdx.x & 31;
        const int vsub = lane >> 3;                // vertex within warp group of 4
        const int oct  = lane & 7;                 // channel octet
        const int gi   = blockIdx.x * 32 + w * 4 + vsub;

        const float4 xa = *(const float4*)(x + (size_t)gi * CC + oct * 8);
        const float4 xb = *(const float4*)(x + (size_t)gi * CC + oct * 8 + 4);
        #pragma unroll
        for (int m = 0; m < MM; ++m) {
            const float4 ua = *(const float4*)(uv_sm + m * 64 + oct * 8);
            const float4 ub = *(const float4*)(uv_sm + m * 64 + oct * 8 + 4);
            const float4 va = *(const float4*)(uv_sm + 576 + m * 64 + oct * 8);
            const float4 vb = *(const float4*)(uv_sm + 576 + m * 64 + oct * 8 + 4);
            float pu = xa.x*ua.x + xa.y*ua.y + xa.z*ua.z + xa.w*ua.w
                     + xb.x*ub.x + xb.y*ub.y + xb.z*ub.z + xb.w*ub.w;
            float pv = xa.x*va.x + xa.y*va.y + xa.z*va.z + xa.w*va.w
                     + xb.x*vb.x + xb.y*vb.y + xb.z*vb.z + xb.w*vb.w;
            pu += __shfl_xor_sync(0xffffffffu, pu, 1);
            pv += __shfl_xor_sync(0xffffffffu, pv, 1);
            pu += __shfl_xor_sync(0xffffffffu, pu, 2);
            pv += __shfl_xor_sync(0xffffffffu, pv, 2);
            pu += __shfl_xor_sync(0xffffffffu, pu, 4);
            pv += __shfl_xor_sync(0xffffffffu, pv, 4);
            if (oct == 0) {
                g_uxc[gi * 12 + m] = pu + c[m];
                g_vxp[gi * 12 + m] = pv;
            }
        }
    } else {
        const int tid = (blockIdx.x - UVX_BLOCKS) * 256 + threadIdx.x;
        if (tid >= MM * OO * CC) return;
        const int cc = tid & 63;
        const int o  = (tid >> 6) & 63;
        const int m  = tid >> 12;
        g_wb[o * GK + m * 64 + cc] = __float2half_rn(W[tid]);
    }
}

// ---------------------------------------------------------------------------
// Kernel 2: gather + softmax + s-accumulate -> g_s (fp16, scl folded)
// ---------------------------------------------------------------------------
__global__ void __launch_bounds__(256)
feast_s(const float* __restrict__ x, const int* __restrict__ adj) {
    __shared__ float q_sm[8 * 384];

    const int tid  = threadIdx.x;
    const int w    = tid >> 5;
    const int lane = tid & 31;
    const int kk   = lane & 15;
    const int vp   = lane >> 4;
    const int bv0  = blockIdx.x * 32;
    float* qbuf = q_sm + w * 384;

    #pragma unroll
    for (int it = 0; it < 2; ++it) {
        const int vpair = w * 4 + it * 2;

        // ---- stage A: lane (vp, kk) -> softmax over M for one neighbor ----
        const int giA  = bv0 + vpair + vp;
        const int base = (giA / NV) * NV;
        const int a    = adj[giA * KN + kk];
        const unsigned bal = __ballot_sync(0xffffffffu, a > 0);
        const int deg0 = __popc(bal & 0xffffu);
        const int deg1 = __popc(bal >> 16);
        const float validf = (a > 0) ? 1.0f : 0.0f;
        const int j0 = (a > 0) ? (base + a - 1) : base;

        const float4 uc0 = *(const float4*)(g_uxc + giA * 12);
        const float4 uc1 = *(const float4*)(g_uxc + giA * 12 + 4);
        const float4 uc2 = *(const float4*)(g_uxc + giA * 12 + 8);
        const float4 vv0 = *(const float4*)(g_vxp + j0 * 12);
        const float4 vv1 = *(const float4*)(g_vxp + j0 * 12 + 4);
        const float4 vv2 = *(const float4*)(g_vxp + j0 * 12 + 8);
        float l[9];
        l[0] = (uc0.x + vv0.x) * validf; l[1] = (uc0.y + vv0.y) * validf;
        l[2] = (uc0.z + vv0.z) * validf; l[3] = (uc0.w + vv0.w) * validf;
        l[4] = (uc1.x + vv1.x) * validf; l[5] = (uc1.y + vv1.y) * validf;
        l[6] = (uc1.z + vv1.z) * validf; l[7] = (uc1.w + vv1.w) * validf;
        l[8] = (uc2.x + vv2.x) * validf;
        float mx = l[0];
        #pragma unroll
        for (int m = 1; m < 9; ++m) mx = fmaxf(mx, l[m]);
        float e[9], ssum = 0.f;
        #pragma unroll
        for (int m = 0; m < 9; ++m) { e[m] = __expf(l[m] - mx); ssum += e[m]; }
        float r;
        asm("rcp.approx.f32 %0, %1;" : "=f"(r) : "f"(ssum));
        r *= validf;

        float* qk = qbuf + (vp * 16 + kk) * 12;
        *(float4*)(qk)     = make_float4(e[0]*r, e[1]*r, e[2]*r, e[3]*r);
        *(float4*)(qk + 4) = make_float4(e[4]*r, e[5]*r, e[6]*r, e[7]*r);
        *(float4*)(qk + 8) = make_float4(e[8]*r, __int_as_float(j0), 0.f, 0.f);
        __syncwarp();

        // ---- stage B: lane <-> channels (lane, lane+32); branchless gathers ----
        #pragma unroll
        for (int vsel = 0; vsel < 2; ++vsel) {
            const float* qb = qbuf + vsel * 192;
            unsigned long long accA[4] = {0ull,0ull,0ull,0ull};
            unsigned long long accB[4] = {0ull,0ull,0ull,0ull};
            float acc8a = 0.f, acc8b = 0.f;
            #pragma unroll 8
            for (int k2 = 0; k2 < KN; ++k2) {
                const ulonglong2 qp0 = *(const ulonglong2*)(qb + k2 * 12);
                const ulonglong2 qp1 = *(const ulonglong2*)(qb + k2 * 12 + 4);
                const float2     qt  = *(const float2*)(qb + k2 * 12 + 8);
                const int j2 = __float_as_int(qt.y);
                const float x0 = x[j2 * CC + lane];
                const float x1 = x[j2 * CC + lane + 32];
                const unsigned long long xx0 = pack2(x0, x0);
                const unsigned long long xx1 = pack2(x1, x1);
                fma2(accA[0], qp0.x, xx0); fma2(accA[1], qp0.y, xx0);
                fma2(accA[2], qp1.x, xx0); fma2(accA[3], qp1.y, xx0);
                fma2(accB[0], qp0.x, xx1); fma2(accB[1], qp0.y, xx1);
                fma2(accB[2], qp1.x, xx1); fma2(accB[3], qp1.y, xx1);
                acc8a = fmaf(qt.x, x0, acc8a);
                acc8b = fmaf(qt.x, x1, acc8b);
            }
            const int dg = vsel ? deg1 : deg0;
            const float scl = (dg > 0) ? (1.0f / (float)dg) : 0.0f;
            __half* srow = g_s + (size_t)(bv0 + vpair + vsel) * GK;
            #pragma unroll
            for (int mp = 0; mp < 4; ++mp) {
                const float2 a0 = unpack2(accA[mp]);
                const float2 b0 = unpack2(accB[mp]);
                srow[(2*mp)   * 64 + lane]      = __float2half_rn(a0.x * scl);
                srow[(2*mp+1) * 64 + lane]      = __float2half_rn(a0.y * scl);
                srow[(2*mp)   * 64 + lane + 32] = __float2half_rn(b0.x * scl);
                srow[(2*mp+1) * 64 + lane + 32] = __float2half_rn(b0.y * scl);
            }
            srow[8 * 64 + lane]      = __float2half_rn(acc8a * scl);
            srow[8 * 64 + lane + 32] = __float2half_rn(acc8b * scl);
        }
        __syncwarp();
    }
}

// ---------------------------------------------------------------------------
// Kernel 3: fp16 HMMA GEMM  out[80000,64] = g_s[.,576] @ g_wb^T + bias
// 128-row x 64-col CTA tile, 8 warps (warp = 16 rows x 64 cols), K chunks of
// 64 halfs (128 B rows), cp.async double-buffered, SW128 swizzle, ldmatrix.x4.
// (byte-level layout identical to the functionally-validated round-8 kernel)
// ---------------------------------------------------------------------------
#define ACHB 16384                       // A chunk: 128 rows x 128 B (64 halfs)
#define BCHB 8192                        // B chunk:  64 rows x 128 B
#define PERBUF (ACHB + BCHB)             // 24576
#define GSMEM (2 * PERBUF + 1024)        // + 1024 alignment slack

__global__ void __launch_bounds__(256, 2)
feast_gemm(const float* __restrict__ bias, float* __restrict__ out) {
    extern __shared__ char smem[];
    const uint32_t sraw = smem_u32(smem);
    const uint32_t sb   = (sraw + 1023u) & ~1023u;     // SW128 needs 1KB align
    const uint32_t abase[2] = { sb, sb + PERBUF };
    const uint32_t bbase[2] = { sb + ACHB, sb + PERBUF + ACHB };

    const int tid  = threadIdx.x;
    const int w    = tid >> 5;
    const int lane = tid & 31;
    const int row0 = blockIdx.x * 128;

    // ldmatrix lane addressing (shared by A and B tiles)
    const int grp = lane >> 3;                 // 0..3 -> matrix index
    const int rr  = lane & 7;                  // row within matrix
    const int mrow = (grp & 1) * 8 + rr;       // row offset within 16-row group
    const int mcol = (grp >> 1) * 16;          // byte col offset (0 or 16)

    // stage K-chunk ch (64 halfs) into buffer b
    auto stage = [&](int ch, int b) {
        const __half* asrc = g_s + (size_t)row0 * GK + ch * 64;
        #pragma unroll
        for (int i = 0; i < 4; ++i) {
            const int uu = tid + i * 256;          // 1024 16B units
            const int row = uu >> 3, cu = uu & 7;
            uint32_t off = (uint32_t)(row * 128 + cu * 16);
            off ^= (off >> 3) & 0x70;
            cpa16(abase[b] + off, asrc + (size_t)row * GK + cu * 8);
        }
        const __half* bsrc = g_wb + ch * 64;
        #pragma unroll
        for (int i = 0; i < 2; ++i) {
            const int uu = tid + i * 256;          // 512 16B units
            const int row = uu >> 3, cu = uu & 7;
            uint32_t off = (uint32_t)(row * 128 + cu * 16);
            off ^= (off >> 3) & 0x70;
            cpa16(bbase[b] + off, bsrc + (size_t)row * GK + cu * 8);
        }
        cpa_commit();
    };

    float acc[8][4];
    #pragma unroll
    for (int j = 0; j < 8; ++j)
        #pragma unroll
        for (int p = 0; p < 4; ++p) acc[j][p] = 0.f;

    stage(0, 0);

    for (int ch = 0; ch < 9; ++ch) {
        cpa_wait0();
        __syncthreads();                       // chunk ch resident; prev buf free

        if (ch < 8) stage(ch + 1, (ch + 1) & 1);

        const uint32_t ab = abase[ch & 1];
        const uint32_t bb = bbase[ch & 1];
        #pragma unroll
        for (int k16 = 0; k16 < 4; ++k16) {    // 16 halfs K per step = 32 bytes
            uint32_t aoff = (uint32_t)((w * 16 + mrow) * 128 + mcol + k16 * 32);
            aoff ^= (aoff >> 3) & 0x70;
            uint32_t a0, a1, a2, a3;
            ldsm4(a0, a1, a2, a3, ab + aoff);
            #pragma unroll
            for (int ng = 0; ng < 4; ++ng) {   // n in groups of 16
                uint32_t boff = (uint32_t)((ng * 16 + mrow) * 128 + mcol + k16 * 32);
                boff ^= (boff >> 3) & 0x70;
                uint32_t b0, b1, b2, b3;
                ldsm4(b0, b1, b2, b3, bb + boff);
                mma16816(acc[ng * 2],     a0, a1, a2, a3, b0, b2);
                mma16816(acc[ng * 2 + 1], a0, a1, a2, a3, b1, b3);
            }
        }
    }

    // ---- epilogue: C frags + bias -> gmem ----
    const int crow = row0 + w * 16 + (lane >> 2);
    const int ccol = (lane & 3) * 2;
    #pragma unroll
    for (int j = 0; j < 8; ++j) {
        const int nb = (j >> 1) * 16 + (j & 1) * 8 + ccol;
        const float2 bv = *(const float2*)(bias + nb);
        *(float2*)(out + (size_t)crow * OO + nb) =
            make_float2(acc[j][0] + bv.x, acc[j][1] + bv.y);
        *(float2*)(out + (size_t)(crow + 8) * OO + nb) =
            make_float2(acc[j][2] + bv.x, acc[j][3] + bv.y);
    }
}

// ---------------------------------------------------------------------------
// Host launcher (graph-capturable: kernel launches only)
// ---------------------------------------------------------------------------
extern "C" void kernel_launch(void* const* d_in, const int* in_sizes, int n_in,
                              void* d_out, int out_size) {
    const float* x   = (const float*)d_in[0];  // [B,N,C]
    const int*   adj = (const int*)  d_in[1];  // [B,N,K]
    const float* W   = (const float*)d_in[2];  // [M,O,C]
    const float* b   = (const float*)d_in[3];  // [O]
    const float* u   = (const float*)d_in[4];  // [M,C]
    const float* v   = (const float*)d_in[5];  // [M,C]
    const float* c   = (const float*)d_in[6];  // [M]
    float* out = (float*)d_out;

    feast_prep<<<UVX_BLOCKS + (MM * OO * CC + 255) / 256, 256>>>(x, u, v, c, W);
    feast_s<<<NVT / 32, 256>>>(x, adj);

    cudaFuncSetAttribute(feast_gemm, cudaFuncAttributeMaxDynamicSharedMemorySize,
                         GSMEM);
    feast_gemm<<<NVT / 128, 256, GSMEM>>>(b, out);
}